// round 14
// baseline (speedup 1.0000x reference)
#include <cuda_runtime.h>
#include <cuda_fp16.h>
#include <cstddef>
#include <cstdint>

#define N_NODES 100000
#define N_EDGES 1600000
#define DIM     128
#define DOUT    64

typedef unsigned long long u64;

// ---------------- scratch (device globals; no allocation allowed) ----------
__device__ __align__(16) float  g_bufB[(size_t)N_NODES * DIM];   // fp32 activations
__device__ __align__(16) __half g_bufH[(size_t)N_NODES * DIM];   // fp16 msgs (pre-scaled by dinv[src])
__device__ int   g_deg[N_NODES];
__device__ int   g_rowstart[N_NODES];
__device__ int   g_cursor[N_NODES];
__device__ int   g_csr_src[N_EDGES];    // src only (norm factored out)
__device__ int   g_total;

// ---------------- degree / CSR ----------------------------------------------
__global__ void k_deg_count(const int* __restrict__ ei) {
    int e = blockIdx.x * blockDim.x + threadIdx.x;
    if (e < N_EDGES) atomicAdd(&g_deg[ei[N_EDGES + e]], 1);
}

// block-parallel range allocation: one atomicAdd per block; range ORDER is
// irrelevant (CSR fill order is already arbitrary).
__global__ void __launch_bounds__(1024) k_rowstart() {
    int i    = blockIdx.x * 1024 + threadIdx.x;
    int lane = threadIdx.x & 31;
    int wid  = threadIdx.x >> 5;
    int deg  = (i < N_NODES) ? g_deg[i] : 0;

    int v = deg;
#pragma unroll
    for (int off = 1; off < 32; off <<= 1) {
        int t = __shfl_up_sync(0xffffffffu, v, off);
        if (lane >= off) v += t;
    }
    __shared__ int wsum[32];
    __shared__ int base;
    if (lane == 31) wsum[wid] = v;
    __syncthreads();
    if (wid == 0) {
        int wv = wsum[lane];
#pragma unroll
        for (int off = 1; off < 32; off <<= 1) {
            int t = __shfl_up_sync(0xffffffffu, wv, off);
            if (lane >= off) wv += t;
        }
        wsum[lane] = wv;
        if (lane == 31) base = atomicAdd(&g_total, wv);
    }
    __syncthreads();
    int excl = base + (wid > 0 ? wsum[wid - 1] : 0) + v - deg;
    if (i < N_NODES) {
        g_rowstart[i] = excl;
        g_cursor[i]   = excl;
    }
}

__global__ void k_csr_fill(const int* __restrict__ ei) {
    int e = blockIdx.x * blockDim.x + threadIdx.x;
    if (e >= N_EDGES) return;
    int s = ei[e];
    int d = ei[N_EDGES + e];
    int pos = atomicAdd(&g_cursor[d], 1);
    g_csr_src[pos] = s;
}

// ---------------- GEMM: Y[n,NCOL] = X[n,128] @ W[128,NCOL] (+bias) ---------
// R4 design (proven): 32-row blocks, 256 threads, f32x2 FMAs; fma pipe is the
// binder. OUT_MODE: 0 = fp32 (fc), 1 = fp16 messages pre-scaled by
// dinv[row] = rsqrt(deg+1) (recomputed here; no dinv array).
template <int NCOL, bool BIAS, int OUT_MODE>
__global__ void __launch_bounds__(256) k_gemm(
    const float* __restrict__ X, const float* __restrict__ W,
    const float* __restrict__ bias, float* __restrict__ Y,
    __half* __restrict__ Yh, int nrows)
{
    constexpr int CG  = NCOL / 4;     // float4 column groups (32 or 16)
    constexpr int RG  = 256 / CG;     // row groups (8 or 16)
    constexpr int RPT = 32 / RG;      // rows per thread (4 or 2)

    __shared__ float Ws[64 * NCOL];
    __shared__ float Xs[32 * 68];

    const int tid  = threadIdx.x;
    const int cg   = tid % CG;
    const int rg   = tid / CG;
    const int row0 = blockIdx.x * 32;

    u64 accL[RPT], accH[RPT];
#pragma unroll
    for (int r = 0; r < RPT; ++r) { accL[r] = 0ull; accH[r] = 0ull; }

    for (int kt = 0; kt < 2; ++kt) {
        const float4* Wg  = (const float4*)(W + (size_t)kt * 64 * NCOL);
        float4*       Ws4 = (float4*)Ws;
#pragma unroll 4
        for (int i = tid; i < 64 * NCOL / 4; i += 256) Ws4[i] = Wg[i];

        for (int i = tid; i < 32 * 16; i += 256) {
            int r  = i / 16;
            int kk = i % 16;
            float4 v = make_float4(0.f, 0.f, 0.f, 0.f);
            if (row0 + r < nrows)
                v = ((const float4*)(X + (size_t)(row0 + r) * DIM + kt * 64))[kk];
            ((float4*)(Xs + r * 68))[kk] = v;
        }
        __syncthreads();

#pragma unroll 8
        for (int k = 0; k < 64; ++k) {
            ulonglong2 w = *((const ulonglong2*)(Ws + k * NCOL) + cg);
#pragma unroll
            for (int r = 0; r < RPT; ++r) {
                unsigned xu = __float_as_uint(Xs[(rg * RPT + r) * 68 + k]);
                u64 xp;
                asm("mov.b64 %0, {%1, %1};" : "=l"(xp) : "r"(xu));
                asm("fma.rn.f32x2 %0, %1, %2, %0;" : "+l"(accL[r]) : "l"(xp), "l"(w.x));
                asm("fma.rn.f32x2 %0, %1, %2, %0;" : "+l"(accH[r]) : "l"(xp), "l"(w.y));
            }
        }
        __syncthreads();
    }

#pragma unroll
    for (int r = 0; r < RPT; ++r) {
        int row = row0 + rg * RPT + r;
        if (row < nrows) {
            float2 lo, hi;
            asm("mov.b64 {%0, %1}, %2;" : "=f"(lo.x), "=f"(lo.y) : "l"(accL[r]));
            asm("mov.b64 {%0, %1}, %2;" : "=f"(hi.x), "=f"(hi.y) : "l"(accH[r]));
            float4 o = make_float4(lo.x, lo.y, hi.x, hi.y);
            if (BIAS) {
                float4 b = ((const float4*)bias)[cg];
                o.x += b.x; o.y += b.y; o.z += b.z; o.w += b.w;
            }
            if (OUT_MODE == 0) {
                ((float4*)(Y + (size_t)row * NCOL))[cg] = o;
            } else {
                float dv = rsqrtf((float)(g_deg[row] + 1));
                __half2 h0 = __floats2half2_rn(o.x * dv, o.y * dv);
                __half2 h1 = __floats2half2_rn(o.z * dv, o.w * dv);
                uint2 pk;
                __builtin_memcpy(&pk.x, &h0, 4);
                __builtin_memcpy(&pk.y, &h1, 4);
                ((uint2*)(Yh + (size_t)row * NCOL))[cg] = pk;
            }
        }
    }
}

// fp16x2 word -> fp32 add (messages are pre-scaled; no multiply needed)
__device__ __forceinline__ void add_h1(float2& a, uint32_t r) {
    __half2 h; float2 f;
    __builtin_memcpy(&h, &r, 4); f = __half22float2(h);
    a.x += f.x; a.y += f.y;
}

// ---------------- CSR aggregation + self-loop + bias + relu ----------------
// warp per (node, feature-half): each gather is ONE 128B line (uint/lane),
// 8x unroll = 8 in-flight lines/warp (proven footprint) with 2x the warps
// and half the serialized batches vs warp-per-node. Broadcast edge loads
// stay as loads (R12: do not shfl-ify).
__global__ void __launch_bounds__(256) k_aggregate(
    const __half* __restrict__ Ah, float* __restrict__ B,
    const float* __restrict__ bias)
{
    int w    = (blockIdx.x * 256 + threadIdx.x) >> 5;
    int lane = threadIdx.x & 31;
    int node = w >> 1;
    int half = w & 1;
    if (node >= N_NODES) return;

    const uint32_t* AH = (const uint32_t*)Ah;   // 64 uints per 128-half row
    const int base = half * 32 + lane;          // uint index within row
    int beg = g_rowstart[node];
    int cnt = g_deg[node];

    float2 a0 = make_float2(0.f, 0.f), a1 = make_float2(0.f, 0.f);
    float2 a2 = make_float2(0.f, 0.f), a3 = make_float2(0.f, 0.f);

    int j = 0;
    for (; j + 8 <= cnt; j += 8) {
        int s0 = g_csr_src[beg + j + 0];
        int s1 = g_csr_src[beg + j + 1];
        int s2 = g_csr_src[beg + j + 2];
        int s3 = g_csr_src[beg + j + 3];
        int s4 = g_csr_src[beg + j + 4];
        int s5 = g_csr_src[beg + j + 5];
        int s6 = g_csr_src[beg + j + 6];
        int s7 = g_csr_src[beg + j + 7];
        uint32_t r0 = AH[(size_t)s0 * 64 + base];
        uint32_t r1 = AH[(size_t)s1 * 64 + base];
        uint32_t r2 = AH[(size_t)s2 * 64 + base];
        uint32_t r3 = AH[(size_t)s3 * 64 + base];
        uint32_t r4 = AH[(size_t)s4 * 64 + base];
        uint32_t r5 = AH[(size_t)s5 * 64 + base];
        uint32_t r6 = AH[(size_t)s6 * 64 + base];
        uint32_t r7 = AH[(size_t)s7 * 64 + base];
        add_h1(a0, r0); add_h1(a1, r1); add_h1(a2, r2); add_h1(a3, r3);
        add_h1(a0, r4); add_h1(a1, r5); add_h1(a2, r6); add_h1(a3, r7);
    }
    for (; j + 4 <= cnt; j += 4) {
        int s0 = g_csr_src[beg + j + 0];
        int s1 = g_csr_src[beg + j + 1];
        int s2 = g_csr_src[beg + j + 2];
        int s3 = g_csr_src[beg + j + 3];
        uint32_t r0 = AH[(size_t)s0 * 64 + base];
        uint32_t r1 = AH[(size_t)s1 * 64 + base];
        uint32_t r2 = AH[(size_t)s2 * 64 + base];
        uint32_t r3 = AH[(size_t)s3 * 64 + base];
        add_h1(a0, r0); add_h1(a1, r1); add_h1(a2, r2); add_h1(a3, r3);
    }
    for (; j < cnt; ++j) {
        add_h1(a0, AH[(size_t)g_csr_src[beg + j] * 64 + base]);
    }

    add_h1(a1, AH[(size_t)node * 64 + base]);   // self loop (pre-scaled)
    float dv = rsqrtf((float)(cnt + 1));
    float2 bb = ((const float2*)bias)[base];
    float2 o;
    o.x = fmaxf(((a0.x + a1.x) + (a2.x + a3.x)) * dv + bb.x, 0.f);
    o.y = fmaxf(((a0.y + a1.y) + (a2.y + a3.y)) * dv + bb.y, 0.f);
    ((float2*)(B + (size_t)node * DIM))[base] = o;
}

// ---------------- launch ----------------------------------------------------
extern "C" void kernel_launch(void* const* d_in, const int* in_sizes, int n_in,
                              void* d_out, int out_size)
{
    const float* x    = (const float*)d_in[0];
    const int*   ei   = (const int*)d_in[1];     // int32 (JAX x64 disabled)
    const float* W1   = (const float*)d_in[2];
    const float* b1   = (const float*)d_in[3];
    const float* W2   = (const float*)d_in[4];
    const float* b2   = (const float*)d_in[5];
    const float* fcW  = (const float*)d_in[6];
    const float* fcb  = (const float*)d_in[7];
    float*       out  = (float*)d_out;

    void *pB_, *pH_, *pDeg_, *pTot_;
    cudaGetSymbolAddress(&pB_,  g_bufB);
    cudaGetSymbolAddress(&pH_,  g_bufH);
    cudaGetSymbolAddress(&pDeg_, g_deg);
    cudaGetSymbolAddress(&pTot_, g_total);
    float*  bufB = (float*)pB_;
    __half* bufH = (__half*)pH_;

    const int TB = 256;
    const int gE  = (N_EDGES + TB - 1) / TB;
    const int gG  = (N_NODES + 31) / 32;              // 32-row gemm tiles
    const int gAg = (N_NODES * 2 * 32 + TB - 1) / TB; // warp per (node,half)
    const int gRS = (N_NODES + 1023) / 1024;

    // zero deg + total via graph-legal async memsets, then count degrees
    cudaMemsetAsync(pDeg_, 0, (size_t)N_NODES * sizeof(int), 0);
    cudaMemsetAsync(pTot_, 0, sizeof(int), 0);
    k_deg_count<<<gE, TB>>>(ei);

    // fork: rowstart+csr_fill on side stream, concurrent with GEMM1
    // (GEMM1 needs only g_deg, which deg_count finalized)
    cudaStream_t sCsr;
    cudaStreamCreateWithFlags(&sCsr, cudaStreamNonBlocking);
    cudaEvent_t evFork, evCsrDone;
    cudaEventCreateWithFlags(&evFork,    cudaEventDisableTiming);
    cudaEventCreateWithFlags(&evCsrDone, cudaEventDisableTiming);

    cudaEventRecord(evFork, 0);
    cudaStreamWaitEvent(sCsr, evFork, 0);
    k_rowstart<<<gRS, 1024, 0, sCsr>>>();
    k_csr_fill<<<gE, TB, 0, sCsr>>>(ei);
    cudaEventRecord(evCsrDone, sCsr);

    // layer 1
    k_gemm<DIM, false, 1><<<gG, TB>>>(x, W1, nullptr, nullptr, bufH, N_NODES);
    cudaStreamWaitEvent(0, evCsrDone, 0);
    k_aggregate<<<gAg, TB>>>(bufH, bufB, b1);

    // layer 2
    k_gemm<DIM, false, 1><<<gG, TB>>>(bufB, W2, nullptr, nullptr, bufH, N_NODES);
    k_aggregate<<<gAg, TB>>>(bufH, bufB, b2);

    // fc (fp32 exact)
    k_gemm<DOUT, true, 0><<<gG, TB>>>(bufB, fcW, fcb, out, nullptr, N_NODES);

    cudaEventDestroy(evFork);
    cudaEventDestroy(evCsrDone);
    cudaStreamDestroy(sCsr);
}